// round 9
// baseline (speedup 1.0000x reference)
#include <cuda_runtime.h>
#include <cuda_bf16.h>
#include <mma.h>
#include <cstdint>
#include <cstddef>

using namespace nvcuda;

// ---------------------------------------------------------------------------
// Problem constants
// ---------------------------------------------------------------------------
#define K_DIM   49152
#define N_DIM   2048
#define N_WAY   64
#define N_SUP   1024
#define N_QRY   2048
#define M_TOT   2112             // 64 protos + 2048 queries
#define M_PAD   2176             // 17 * 128 (pad rows stay zero)
#define EPS_CS  1e-6f

// GEMM tiling
#define BM 128
#define BN 128
#define BK 32
#define CHUNKS (K_DIM / BK)      // 1536 (divisible by 3)
#define STAGES 3
#define LDA 40                   // 32 + 8 pad (bf16), row = 80B (16B aligned)
#define LDB 136                  // 128 + 8 pad (bf16), row = 272B (16B aligned)

// Per-stage smem byte offsets
#define AH_OFF 0
#define AL_OFF (BM * LDA * 2)                    // 10240
#define BH_OFF (2 * BM * LDA * 2)                // 20480
#define BL_OFF (2 * BM * LDA * 2 + BK * LDB * 2) // 29184
#define STAGE_B (2 * BM * LDA * 2 + 2 * BK * LDB * 2)   // 37888
#define DSMEM_BYTES (STAGES * STAGE_B)                  // 113664

// ---------------------------------------------------------------------------
// Device scratch (no cudaMalloc allowed; globals are zero-initialized)
// ---------------------------------------------------------------------------
__device__ __align__(16)  float         g_protoA[N_WAY * K_DIM];
__device__ __align__(16)  float         g_Z[M_TOT * N_DIM];
__device__                float         g_norms[M_TOT];
__device__ __align__(128) __nv_bfloat16 g_Xh[(size_t)M_PAD * K_DIM];
__device__ __align__(128) __nv_bfloat16 g_Xl[(size_t)M_PAD * K_DIM];
__device__ __align__(128) __nv_bfloat16 g_Wh[(size_t)K_DIM * N_DIM];
__device__ __align__(128) __nv_bfloat16 g_Wl[(size_t)K_DIM * N_DIM];

// ---------------------------------------------------------------------------
// Helpers
// ---------------------------------------------------------------------------
__device__ __forceinline__ uint32_t smem_u32(const void* p) {
    uint32_t a;
    asm("{ .reg .u64 t; cvta.to.shared.u64 t, %1; cvt.u32.u64 %0, t; }" : "=r"(a) : "l"(p));
    return a;
}
__device__ __forceinline__ void cp_async16(uint32_t dst, const void* src) {
    asm volatile("cp.async.cg.shared.global [%0], [%1], 16;" :: "r"(dst), "l"(src) : "memory");
}
__device__ __forceinline__ void cp_commit() {
    asm volatile("cp.async.commit_group;" ::: "memory");
}
template <int N>
__device__ __forceinline__ void cp_wait() {
    asm volatile("cp.async.wait_group %0;" :: "n"(N) : "memory");
}

// f32x4 -> packed hi bf16x4 (8B) + residual float4
__device__ __forceinline__ unsigned long long pack4_hi(float4 v, float4* rem) {
    __nv_bfloat16 h0 = __float2bfloat16(v.x), h1 = __float2bfloat16(v.y);
    __nv_bfloat16 h2 = __float2bfloat16(v.z), h3 = __float2bfloat16(v.w);
    rem->x = v.x - __bfloat162float(h0);
    rem->y = v.y - __bfloat162float(h1);
    rem->z = v.z - __bfloat162float(h2);
    rem->w = v.w - __bfloat162float(h3);
    unsigned a = (unsigned)__bfloat16_as_ushort(h0) | ((unsigned)__bfloat16_as_ushort(h1) << 16);
    unsigned b = (unsigned)__bfloat16_as_ushort(h2) | ((unsigned)__bfloat16_as_ushort(h3) << 16);
    return (unsigned long long)a | ((unsigned long long)b << 32);
}
__device__ __forceinline__ unsigned long long pack4(float4 v) {
    __nv_bfloat16 h0 = __float2bfloat16(v.x), h1 = __float2bfloat16(v.y);
    __nv_bfloat16 h2 = __float2bfloat16(v.z), h3 = __float2bfloat16(v.w);
    unsigned a = (unsigned)__bfloat16_as_ushort(h0) | ((unsigned)__bfloat16_as_ushort(h1) << 16);
    unsigned b = (unsigned)__bfloat16_as_ushort(h2) | ((unsigned)__bfloat16_as_ushort(h3) << 16);
    return (unsigned long long)a | ((unsigned long long)b << 32);
}

// ---------------------------------------------------------------------------
// Kernel 1: per-class mean of support images. grid (64, 16), block 256
// ---------------------------------------------------------------------------
__global__ void proto_mean_kernel(const float* __restrict__ support,
                                  const int* __restrict__ labels) {
    __shared__ int s_rows[N_SUP];
    __shared__ int s_cnt;
    const int c   = blockIdx.x;
    const int tid = threadIdx.x;

    if (tid < 32) {
        int cnt = 0;
        for (int base = 0; base < N_SUP; base += 32) {
            int lab = labels[base + tid];
            unsigned m = __ballot_sync(0xffffffffu, lab == c);
            if (lab == c)
                s_rows[cnt + __popc(m & ((1u << tid) - 1u))] = base + tid;
            cnt += __popc(m);
        }
        if (tid == 0) s_cnt = cnt;
    }
    __syncthreads();

    const int   n   = s_cnt;
    const float inv = 1.0f / (float)n;
    const int kchunk = K_DIM / gridDim.y;
    const int k0     = blockIdx.y * kchunk;

    for (int k = k0 + tid; k < k0 + kchunk; k += blockDim.x) {
        float s = 0.0f;
        for (int j = 0; j < n; j++)
            s += support[(size_t)s_rows[j] * K_DIM + k];
        g_protoA[c * K_DIM + k] = s * inv;
    }
}

// ---------------------------------------------------------------------------
// Kernel 2: split-convert X rows (protos first, then queries). grid 2112.
// ---------------------------------------------------------------------------
__global__ void convert_X_kernel(const float* __restrict__ query) {
    const int row = blockIdx.x;
    const float* src = (row < N_WAY) ? &g_protoA[(size_t)row * K_DIM]
                                     : &query[(size_t)(row - N_WAY) * K_DIM];
    __nv_bfloat16* dh = &g_Xh[(size_t)row * K_DIM];
    __nv_bfloat16* dl = &g_Xl[(size_t)row * K_DIM];
    for (int k4 = threadIdx.x * 4; k4 < K_DIM; k4 += blockDim.x * 4) {
        float4 v = *reinterpret_cast<const float4*>(&src[k4]);
        float4 rem;
        unsigned long long hi = pack4_hi(v, &rem);
        unsigned long long lo = pack4(rem);
        *reinterpret_cast<unsigned long long*>(&dh[k4]) = hi;
        *reinterpret_cast<unsigned long long*>(&dl[k4]) = lo;
    }
}

// ---------------------------------------------------------------------------
// Kernel 3: split-convert W (flat, layout preserved). grid 98304, block 256.
// ---------------------------------------------------------------------------
__global__ void convert_W_kernel(const float* __restrict__ W) {
    const size_t i4 = ((size_t)blockIdx.x * blockDim.x + threadIdx.x) * 4;
    float4 v = *reinterpret_cast<const float4*>(&W[i4]);
    float4 rem;
    unsigned long long hi = pack4_hi(v, &rem);
    unsigned long long lo = pack4(rem);
    *reinterpret_cast<unsigned long long*>(&g_Wh[i4]) = hi;
    *reinterpret_cast<unsigned long long*>(&g_Wl[i4]) = lo;
}

// ---------------------------------------------------------------------------
// Kernel 4: GEMM  Z[M_PAD, 2048] = X @ W  (3xbf16 split, f32 acc)
// grid (16 n-tiles, 17 m-tiles), block 256, 3-stage cp.async pipeline.
// One barrier per chunk; cp.async issue interleaved under the MMA stream.
// ---------------------------------------------------------------------------
__device__ __forceinline__ void issue_A(int c, uint32_t sb, int m0, int tid) {
    const int k0 = c * BK;
#pragma unroll
    for (int i = 0; i < 2; i++) {
        int idx = tid + i * 256;            // 0..511
        int r   = idx >> 2;                 // 0..127
        int seg = (idx & 3) * 8;            // bf16 elems (16B segs)
        uint32_t doff = (uint32_t)(r * LDA + seg) * 2u;
        cp_async16(sb + AH_OFF + doff, &g_Xh[(size_t)(m0 + r) * K_DIM + k0 + seg]);
        cp_async16(sb + AL_OFF + doff, &g_Xl[(size_t)(m0 + r) * K_DIM + k0 + seg]);
    }
}
__device__ __forceinline__ void issue_B(int c, uint32_t sb, int n0, int tid) {
    const int k0 = c * BK;
#pragma unroll
    for (int i = 0; i < 2; i++) {
        int idx = tid + i * 256;            // 0..511
        int r   = idx >> 4;                 // 0..31
        int seg = (idx & 15) * 8;
        uint32_t doff = (uint32_t)(r * LDB + seg) * 2u;
        cp_async16(sb + BH_OFF + doff, &g_Wh[(size_t)(k0 + r) * N_DIM + n0 + seg]);
        cp_async16(sb + BL_OFF + doff, &g_Wl[(size_t)(k0 + r) * N_DIM + n0 + seg]);
    }
}

__global__ void __launch_bounds__(256, 2) gemm_wmma_kernel() {
    extern __shared__ char dsm[];
    const uint32_t smem_base = smem_u32(dsm);

    const int tid = threadIdx.x;
    const int n0  = blockIdx.x * BN;
    const int m0  = blockIdx.y * BM;
    const int warpId = tid >> 5;
    const int wm = warpId >> 2;   // 0..1 (64 rows)
    const int wn = warpId & 3;    // 0..3 (32 cols)

    wmma::fragment<wmma::accumulator, 16, 16, 16, float> acc[4][2];
#pragma unroll
    for (int mi = 0; mi < 4; mi++)
#pragma unroll
        for (int ni = 0; ni < 2; ni++)
            wmma::fill_fragment(acc[mi][ni], 0.0f);

    // prologue: 2 stages in flight
    issue_A(0, smem_base + 0 * STAGE_B, m0, tid);
    issue_B(0, smem_base + 0 * STAGE_B, n0, tid);
    cp_commit();
    issue_A(1, smem_base + 1 * STAGE_B, m0, tid);
    issue_B(1, smem_base + 1 * STAGE_B, n0, tid);
    cp_commit();

    // one chunk body; stage offsets are compile-time via the 3x manual unroll
#define CHUNK_BODY(c, S)                                                              \
    {                                                                                 \
        cp_wait<1>();                                                                 \
        __syncthreads();                                                              \
        const char* sb = dsm + (S) * STAGE_B;                                         \
        const uint32_t sbN = smem_base + (uint32_t)(((S) + 2) % STAGES) * STAGE_B;    \
        const __nv_bfloat16* Ah = (const __nv_bfloat16*)(sb + AH_OFF);                \
        const __nv_bfloat16* Al = (const __nv_bfloat16*)(sb + AL_OFF);                \
        const __nv_bfloat16* Bh = (const __nv_bfloat16*)(sb + BH_OFF);                \
        const __nv_bfloat16* Bl = (const __nv_bfloat16*)(sb + BL_OFF);                \
        const bool pf = ((c) + 2 < CHUNKS);                                           \
        _Pragma("unroll")                                                             \
        for (int ks = 0; ks < 2; ks++) {                                              \
            const int kk = ks * 16;                                                   \
            wmma::fragment<wmma::matrix_a, 16, 16, 16, __nv_bfloat16,                 \
                           wmma::row_major> ah[4], al[4];                             \
            _Pragma("unroll")                                                         \
            for (int mi = 0; mi < 4; mi++) {                                          \
                wmma::load_matrix_sync(ah[mi], &Ah[(wm * 64 + mi * 16) * LDA + kk], LDA); \
                wmma::load_matrix_sync(al[mi], &Al[(wm * 64 + mi * 16) * LDA + kk], LDA); \
            }                                                                         \
            /* deferred prefetch: A-half under k-step 0, B-half under k-step 1 */     \
            if (ks == 0) { if (pf) issue_A((c) + 2, sbN, m0, tid); }                  \
            else         { if (pf) issue_B((c) + 2, sbN, n0, tid); cp_commit(); }     \
            _Pragma("unroll")                                                         \
            for (int ni = 0; ni < 2; ni++) {                                          \
                wmma::fragment<wmma::matrix_b, 16, 16, 16, __nv_bfloat16,             \
                               wmma::row_major> bh, bl;                               \
                wmma::load_matrix_sync(bh, &Bh[kk * LDB + wn * 32 + ni * 16], LDB);   \
                wmma::load_matrix_sync(bl, &Bl[kk * LDB + wn * 32 + ni * 16], LDB);   \
                _Pragma("unroll")                                                     \
                for (int mi = 0; mi < 4; mi++) {                                      \
                    wmma::mma_sync(acc[mi][ni], ah[mi], bh, acc[mi][ni]);             \
                    wmma::mma_sync(acc[mi][ni], ah[mi], bl, acc[mi][ni]);             \
                    wmma::mma_sync(acc[mi][ni], al[mi], bh, acc[mi][ni]);             \
                }                                                                     \
            }                                                                         \
        }                                                                             \
    }

    for (int c = 0; c < CHUNKS; c += 3) {       // CHUNKS % 3 == 0
        CHUNK_BODY(c + 0, 0)
        CHUNK_BODY(c + 1, 1)
        CHUNK_BODY(c + 2, 2)
    }
#undef CHUNK_BODY

    // epilogue: 64-row warp blocks are fully valid or fully padding
    const int rowBase = m0 + wm * 64;
    if (rowBase < M_TOT) {
#pragma unroll
        for (int mi = 0; mi < 4; mi++)
#pragma unroll
            for (int ni = 0; ni < 2; ni++)
                wmma::store_matrix_sync(&g_Z[(size_t)(rowBase + mi * 16) * N_DIM + n0 + wn * 32 + ni * 16],
                                        acc[mi][ni], N_DIM, wmma::mem_row_major);
    }
}

// ---------------------------------------------------------------------------
// Kernel 5: Z += b (in place) and row norms. grid 2112, block 256.
// ---------------------------------------------------------------------------
__global__ void bias_norm_kernel(const float* __restrict__ b) {
    __shared__ float red[256];
    const int m   = blockIdx.x;
    const int tid = threadIdx.x;
    float* z = &g_Z[(size_t)m * N_DIM];
    float acc = 0.0f;
    for (int k = tid; k < N_DIM; k += 256) {
        float v = z[k] + b[k];
        z[k] = v;
        acc += v * v;
    }
    red[tid] = acc;
    __syncthreads();
    for (int s = 128; s > 0; s >>= 1) {
        if (tid < s) red[tid] += red[tid + s];
        __syncthreads();
    }
    if (tid == 0) g_norms[m] = sqrtf(red[0]);
}

// ---------------------------------------------------------------------------
// Kernel 6: cosine scores. grid 2048, block 256.
// ---------------------------------------------------------------------------
__global__ void scores_kernel(float* __restrict__ out) {
    __shared__ float q[N_DIM];
    const int qi   = blockIdx.x;
    const int tid  = threadIdx.x;
    const int warp = tid >> 5;
    const int lane = tid & 31;

    const float* qrow = &g_Z[(size_t)(N_WAY + qi) * N_DIM];
    for (int k = tid; k < N_DIM; k += 256) q[k] = qrow[k];
    __syncthreads();

    const float qn = g_norms[N_WAY + qi];
    for (int c = warp; c < N_WAY; c += 8) {
        const float* p = &g_Z[(size_t)c * N_DIM];
        float acc = 0.0f;
        for (int k = lane; k < N_DIM; k += 32)
            acc += q[k] * p[k];
#pragma unroll
        for (int off = 16; off > 0; off >>= 1)
            acc += __shfl_xor_sync(0xffffffffu, acc, off);
        if (lane == 0) {
            float d = fmaxf(qn * g_norms[c], EPS_CS);
            out[qi * N_WAY + c] = acc / d;
        }
    }
}

// ---------------------------------------------------------------------------
// Launch
// ---------------------------------------------------------------------------
extern "C" void kernel_launch(void* const* d_in, const int* in_sizes, int n_in,
                              void* d_out, int out_size) {
    const float* support = (const float*)d_in[0];   // [1024, 49152] f32
    const int*   labels  = (const int*)  d_in[1];   // [1024] i32
    const float* query   = (const float*)d_in[2];   // [2048, 49152] f32
    const float* W       = (const float*)d_in[3];   // [49152, 2048] f32
    const float* b       = (const float*)d_in[4];   // [2048] f32
    float*       out     = (float*)d_out;           // [2048, 64] f32

    cudaFuncSetAttribute(gemm_wmma_kernel,
                         cudaFuncAttributeMaxDynamicSharedMemorySize, DSMEM_BYTES);

    proto_mean_kernel<<<dim3(N_WAY, 16), 256>>>(support, labels);
    convert_X_kernel<<<M_TOT, 256>>>(query);
    convert_W_kernel<<<(K_DIM / 4) * (N_DIM / 256), 256>>>(W);
    gemm_wmma_kernel<<<dim3(N_DIM / BN, M_PAD / BM), 256, DSMEM_BYTES>>>();
    bias_norm_kernel<<<M_TOT, 256>>>(b);
    scores_kernel<<<N_QRY, 256>>>(out);
}

// round 10
// speedup vs baseline: 1.0843x; 1.0843x over previous
#include <cuda_runtime.h>
#include <cuda_bf16.h>
#include <mma.h>
#include <cstdint>
#include <cstddef>

using namespace nvcuda;

// ---------------------------------------------------------------------------
// Problem constants
// ---------------------------------------------------------------------------
#define K_DIM   49152
#define N_DIM   2048
#define N_WAY   64
#define N_SUP   1024
#define N_QRY   2048
#define M_TOT   2112             // 64 protos + 2048 queries
#define M_PAD   2176             // 17 * 128 (pad rows stay zero)
#define EPS_CS  1e-6f

// GEMM tiling: 136 CTAs (one per SM), 512 threads, warp tile 64x32
#define BM 128
#define BN 256
#define BK 32
#define CHUNKS (K_DIM / BK)      // 1536 (divisible by 3)
#define STAGES 3
#define LDA 40                   // 32 + 8 pad (bf16)
#define LDB 264                  // 256 + 8 pad (bf16)

// Per-stage smem byte offsets
#define AH_OFF 0
#define AL_OFF (BM * LDA * 2)                    // 10240
#define BH_OFF (2 * BM * LDA * 2)                // 20480
#define BL_OFF (2 * BM * LDA * 2 + BK * LDB * 2) // 37376
#define STAGE_B (2 * BM * LDA * 2 + 2 * BK * LDB * 2)   // 54272
#define DSMEM_BYTES (STAGES * STAGE_B)                  // 162816

// ---------------------------------------------------------------------------
// Device scratch (no cudaMalloc allowed; globals are zero-initialized)
// ---------------------------------------------------------------------------
__device__ __align__(16)  float         g_protoA[N_WAY * K_DIM];
__device__ __align__(16)  float         g_Z[M_TOT * N_DIM];
__device__                float         g_norms[M_TOT];
__device__ __align__(128) __nv_bfloat16 g_Xh[(size_t)M_PAD * K_DIM];
__device__ __align__(128) __nv_bfloat16 g_Xl[(size_t)M_PAD * K_DIM];
__device__ __align__(128) __nv_bfloat16 g_Wh[(size_t)K_DIM * N_DIM];
__device__ __align__(128) __nv_bfloat16 g_Wl[(size_t)K_DIM * N_DIM];

// ---------------------------------------------------------------------------
// Helpers
// ---------------------------------------------------------------------------
__device__ __forceinline__ uint32_t smem_u32(const void* p) {
    uint32_t a;
    asm("{ .reg .u64 t; cvta.to.shared.u64 t, %1; cvt.u32.u64 %0, t; }" : "=r"(a) : "l"(p));
    return a;
}
__device__ __forceinline__ void cp_async16(uint32_t dst, const void* src) {
    asm volatile("cp.async.cg.shared.global [%0], [%1], 16;" :: "r"(dst), "l"(src) : "memory");
}
__device__ __forceinline__ void cp_commit() {
    asm volatile("cp.async.commit_group;" ::: "memory");
}
template <int N>
__device__ __forceinline__ void cp_wait() {
    asm volatile("cp.async.wait_group %0;" :: "n"(N) : "memory");
}

// f32x4 -> packed hi bf16x4 (8B) + residual float4
__device__ __forceinline__ unsigned long long pack4_hi(float4 v, float4* rem) {
    __nv_bfloat16 h0 = __float2bfloat16(v.x), h1 = __float2bfloat16(v.y);
    __nv_bfloat16 h2 = __float2bfloat16(v.z), h3 = __float2bfloat16(v.w);
    rem->x = v.x - __bfloat162float(h0);
    rem->y = v.y - __bfloat162float(h1);
    rem->z = v.z - __bfloat162float(h2);
    rem->w = v.w - __bfloat162float(h3);
    unsigned a = (unsigned)__bfloat16_as_ushort(h0) | ((unsigned)__bfloat16_as_ushort(h1) << 16);
    unsigned b = (unsigned)__bfloat16_as_ushort(h2) | ((unsigned)__bfloat16_as_ushort(h3) << 16);
    return (unsigned long long)a | ((unsigned long long)b << 32);
}
__device__ __forceinline__ unsigned long long pack4(float4 v) {
    __nv_bfloat16 h0 = __float2bfloat16(v.x), h1 = __float2bfloat16(v.y);
    __nv_bfloat16 h2 = __float2bfloat16(v.z), h3 = __float2bfloat16(v.w);
    unsigned a = (unsigned)__bfloat16_as_ushort(h0) | ((unsigned)__bfloat16_as_ushort(h1) << 16);
    unsigned b = (unsigned)__bfloat16_as_ushort(h2) | ((unsigned)__bfloat16_as_ushort(h3) << 16);
    return (unsigned long long)a | ((unsigned long long)b << 32);
}

// ---------------------------------------------------------------------------
// Kernel 1: per-class mean of support images. grid (64, 16), block 256
// ---------------------------------------------------------------------------
__global__ void proto_mean_kernel(const float* __restrict__ support,
                                  const int* __restrict__ labels) {
    __shared__ int s_rows[N_SUP];
    __shared__ int s_cnt;
    const int c   = blockIdx.x;
    const int tid = threadIdx.x;

    if (tid < 32) {
        int cnt = 0;
        for (int base = 0; base < N_SUP; base += 32) {
            int lab = labels[base + tid];
            unsigned m = __ballot_sync(0xffffffffu, lab == c);
            if (lab == c)
                s_rows[cnt + __popc(m & ((1u << tid) - 1u))] = base + tid;
            cnt += __popc(m);
        }
        if (tid == 0) s_cnt = cnt;
    }
    __syncthreads();

    const int   n   = s_cnt;
    const float inv = 1.0f / (float)n;
    const int kchunk = K_DIM / gridDim.y;
    const int k0     = blockIdx.y * kchunk;

    for (int k = k0 + tid; k < k0 + kchunk; k += blockDim.x) {
        float s = 0.0f;
        for (int j = 0; j < n; j++)
            s += support[(size_t)s_rows[j] * K_DIM + k];
        g_protoA[c * K_DIM + k] = s * inv;
    }
}

// ---------------------------------------------------------------------------
// Kernel 2: split-convert X rows (protos first, then queries). grid 2112.
// ---------------------------------------------------------------------------
__global__ void convert_X_kernel(const float* __restrict__ query) {
    const int row = blockIdx.x;
    const float* src = (row < N_WAY) ? &g_protoA[(size_t)row * K_DIM]
                                     : &query[(size_t)(row - N_WAY) * K_DIM];
    __nv_bfloat16* dh = &g_Xh[(size_t)row * K_DIM];
    __nv_bfloat16* dl = &g_Xl[(size_t)row * K_DIM];
    for (int k4 = threadIdx.x * 4; k4 < K_DIM; k4 += blockDim.x * 4) {
        float4 v = *reinterpret_cast<const float4*>(&src[k4]);
        float4 rem;
        unsigned long long hi = pack4_hi(v, &rem);
        unsigned long long lo = pack4(rem);
        *reinterpret_cast<unsigned long long*>(&dh[k4]) = hi;
        *reinterpret_cast<unsigned long long*>(&dl[k4]) = lo;
    }
}

// ---------------------------------------------------------------------------
// Kernel 3: split-convert W (flat, layout preserved). grid 98304, block 256.
// ---------------------------------------------------------------------------
__global__ void convert_W_kernel(const float* __restrict__ W) {
    const size_t i4 = ((size_t)blockIdx.x * blockDim.x + threadIdx.x) * 4;
    float4 v = *reinterpret_cast<const float4*>(&W[i4]);
    float4 rem;
    unsigned long long hi = pack4_hi(v, &rem);
    unsigned long long lo = pack4(rem);
    *reinterpret_cast<unsigned long long*>(&g_Wh[i4]) = hi;
    *reinterpret_cast<unsigned long long*>(&g_Wl[i4]) = lo;
}

// ---------------------------------------------------------------------------
// Kernel 4: GEMM  Z[M_PAD, 2048] = X @ W  (3xbf16 split, f32 acc)
// grid (8 n-tiles, 17 m-tiles) = 136 CTAs (1/SM), block 512,
// 3-stage cp.async pipeline, one barrier per chunk.
// ---------------------------------------------------------------------------
__device__ __forceinline__ void issue_stage(int c, uint32_t sb, int m0, int n0, int tid) {
    const int k0 = c * BK;
    // A: 128 rows x 32 cols bf16 = 4 x 16B segs/row; 512 idx, 1 per thread (hi+lo)
    {
        int r   = tid >> 2;                 // 0..127
        int seg = (tid & 3) * 8;            // bf16 elems
        uint32_t doff = (uint32_t)(r * LDA + seg) * 2u;
        cp_async16(sb + AH_OFF + doff, &g_Xh[(size_t)(m0 + r) * K_DIM + k0 + seg]);
        cp_async16(sb + AL_OFF + doff, &g_Xl[(size_t)(m0 + r) * K_DIM + k0 + seg]);
    }
    // B: 32 rows x 256 cols bf16 = 32 x 16B segs/row; 1024 idx, 2 per thread (hi+lo)
#pragma unroll
    for (int i = 0; i < 2; i++) {
        int idx = tid + i * 512;            // 0..1023
        int r   = idx >> 5;                 // 0..31
        int seg = (idx & 31) * 8;
        uint32_t doff = (uint32_t)(r * LDB + seg) * 2u;
        cp_async16(sb + BH_OFF + doff, &g_Wh[(size_t)(k0 + r) * N_DIM + n0 + seg]);
        cp_async16(sb + BL_OFF + doff, &g_Wl[(size_t)(k0 + r) * N_DIM + n0 + seg]);
    }
    cp_commit();
}

__global__ void __launch_bounds__(512, 1) gemm_wmma_kernel() {
    extern __shared__ char dsm[];
    const uint32_t smem_base = smem_u32(dsm);

    const int tid = threadIdx.x;
    const int n0  = blockIdx.x * BN;
    const int m0  = blockIdx.y * BM;
    const int warpId = tid >> 5;        // 0..15
    const int wm = warpId >> 3;         // 0..1 (64 rows)
    const int wn = warpId & 7;          // 0..7 (32 cols)

    wmma::fragment<wmma::accumulator, 16, 16, 16, float> acc[4][2];
#pragma unroll
    for (int mi = 0; mi < 4; mi++)
#pragma unroll
        for (int ni = 0; ni < 2; ni++)
            wmma::fill_fragment(acc[mi][ni], 0.0f);

    // prologue: 2 stages in flight
    issue_stage(0, smem_base + 0 * STAGE_B, m0, n0, tid);
    issue_stage(1, smem_base + 1 * STAGE_B, m0, n0, tid);

#define CHUNK_BODY(c, S)                                                              \
    {                                                                                 \
        cp_wait<1>();                                                                 \
        __syncthreads();                                                              \
        if ((c) + 2 < CHUNKS)                                                         \
            issue_stage((c) + 2, smem_base + (uint32_t)(((S) + 2) % STAGES) * STAGE_B,\
                        m0, n0, tid);                                                 \
        const char* sb = dsm + (S) * STAGE_B;                                         \
        const __nv_bfloat16* Ah = (const __nv_bfloat16*)(sb + AH_OFF);                \
        const __nv_bfloat16* Al = (const __nv_bfloat16*)(sb + AL_OFF);                \
        const __nv_bfloat16* Bh = (const __nv_bfloat16*)(sb + BH_OFF);                \
        const __nv_bfloat16* Bl = (const __nv_bfloat16*)(sb + BL_OFF);                \
        _Pragma("unroll")                                                             \
        for (int ks = 0; ks < 2; ks++) {                                              \
            const int kk = ks * 16;                                                   \
            wmma::fragment<wmma::matrix_a, 16, 16, 16, __nv_bfloat16,                 \
                           wmma::row_major> ah[4], al[4];                             \
            _Pragma("unroll")                                                         \
            for (int mi = 0; mi < 4; mi++) {                                          \
                wmma::load_matrix_sync(ah[mi], &Ah[(wm * 64 + mi * 16) * LDA + kk], LDA); \
                wmma::load_matrix_sync(al[mi], &Al[(wm * 64 + mi * 16) * LDA + kk], LDA); \
            }                                                                         \
            _Pragma("unroll")                                                         \
            for (int ni = 0; ni < 2; ni++) {                                          \
                wmma::fragment<wmma::matrix_b, 16, 16, 16, __nv_bfloat16,             \
                               wmma::row_major> bh, bl;                               \
                wmma::load_matrix_sync(bh, &Bh[kk * LDB + wn * 32 + ni * 16], LDB);   \
                wmma::load_matrix_sync(bl, &Bl[kk * LDB + wn * 32 + ni * 16], LDB);   \
                _Pragma("unroll")                                                     \
                for (int mi = 0; mi < 4; mi++) {                                      \
                    wmma::mma_sync(acc[mi][ni], ah[mi], bh, acc[mi][ni]);             \
                    wmma::mma_sync(acc[mi][ni], ah[mi], bl, acc[mi][ni]);             \
                    wmma::mma_sync(acc[mi][ni], al[mi], bh, acc[mi][ni]);             \
                }                                                                     \
            }                                                                         \
        }                                                                             \
    }

    for (int c = 0; c < CHUNKS; c += 3) {       // CHUNKS % 3 == 0
        CHUNK_BODY(c + 0, 0)
        CHUNK_BODY(c + 1, 1)
        CHUNK_BODY(c + 2, 2)
    }
#undef CHUNK_BODY

    cp_wait<0>();

    // epilogue: 64-row warp blocks are fully valid or fully padding (M_TOT%64==0)
    const int rowBase = m0 + wm * 64;
    if (rowBase < M_TOT) {
#pragma unroll
        for (int mi = 0; mi < 4; mi++)
#pragma unroll
            for (int ni = 0; ni < 2; ni++)
                wmma::store_matrix_sync(&g_Z[(size_t)(rowBase + mi * 16) * N_DIM + n0 + wn * 32 + ni * 16],
                                        acc[mi][ni], N_DIM, wmma::mem_row_major);
    }
}

// ---------------------------------------------------------------------------
// Kernel 5: Z += b (in place) and row norms. grid 2112, block 256.
// ---------------------------------------------------------------------------
__global__ void bias_norm_kernel(const float* __restrict__ b) {
    __shared__ float red[256];
    const int m   = blockIdx.x;
    const int tid = threadIdx.x;
    float* z = &g_Z[(size_t)m * N_DIM];
    float acc = 0.0f;
    for (int k = tid; k < N_DIM; k += 256) {
        float v = z[k] + b[k];
        z[k] = v;
        acc += v * v;
    }
    red[tid] = acc;
    __syncthreads();
    for (int s = 128; s > 0; s >>= 1) {
        if (tid < s) red[tid] += red[tid + s];
        __syncthreads();
    }
    if (tid == 0) g_norms[m] = sqrtf(red[0]);
}

// ---------------------------------------------------------------------------
// Kernel 6: cosine scores. grid 2048, block 256.
// ---------------------------------------------------------------------------
__global__ void scores_kernel(float* __restrict__ out) {
    __shared__ float q[N_DIM];
    const int qi   = blockIdx.x;
    const int tid  = threadIdx.x;
    const int warp = tid >> 5;
    const int lane = tid & 31;

    const float* qrow = &g_Z[(size_t)(N_WAY + qi) * N_DIM];
    for (int k = tid; k < N_DIM; k += 256) q[k] = qrow[k];
    __syncthreads();

    const float qn = g_norms[N_WAY + qi];
    for (int c = warp; c < N_WAY; c += 8) {
        const float* p = &g_Z[(size_t)c * N_DIM];
        float acc = 0.0f;
        for (int k = lane; k < N_DIM; k += 32)
            acc += q[k] * p[k];
#pragma unroll
        for (int off = 16; off > 0; off >>= 1)
            acc += __shfl_xor_sync(0xffffffffu, acc, off);
        if (lane == 0) {
            float d = fmaxf(qn * g_norms[c], EPS_CS);
            out[qi * N_WAY + c] = acc / d;
        }
    }
}

// ---------------------------------------------------------------------------
// Launch
// ---------------------------------------------------------------------------
extern "C" void kernel_launch(void* const* d_in, const int* in_sizes, int n_in,
                              void* d_out, int out_size) {
    const float* support = (const float*)d_in[0];   // [1024, 49152] f32
    const int*   labels  = (const int*)  d_in[1];   // [1024] i32
    const float* query   = (const float*)d_in[2];   // [2048, 49152] f32
    const float* W       = (const float*)d_in[3];   // [49152, 2048] f32
    const float* b       = (const float*)d_in[4];   // [2048] f32
    float*       out     = (float*)d_out;           // [2048, 64] f32

    cudaFuncSetAttribute(gemm_wmma_kernel,
                         cudaFuncAttributeMaxDynamicSharedMemorySize, DSMEM_BYTES);

    proto_mean_kernel<<<dim3(N_WAY, 16), 256>>>(support, labels);
    convert_X_kernel<<<M_TOT, 256>>>(query);
    convert_W_kernel<<<(K_DIM / 4) * (N_DIM / 256), 256>>>(W);
    gemm_wmma_kernel<<<dim3(N_DIM / BN, M_PAD / BM), 512, DSMEM_BYTES>>>();
    bias_norm_kernel<<<M_TOT, 256>>>(b);
    scores_kernel<<<N_QRY, 256>>>(out);
}

// round 12
// speedup vs baseline: 1.1094x; 1.0232x over previous
#include <cuda_runtime.h>
#include <cuda_bf16.h>
#include <mma.h>
#include <cstdint>
#include <cstddef>

using namespace nvcuda;

// ---------------------------------------------------------------------------
// Problem constants
// ---------------------------------------------------------------------------
#define K_DIM   49152
#define N_DIM   2048
#define N_WAY   64
#define N_SUP   1024
#define N_QRY   2048
#define M_TOT   2112             // 64 protos + 2048 queries
#define M_PAD   2176             // 17 * 128 (pad rows stay zero)
#define EPS_CS  1e-6f

// GEMM tiling: 136 CTAs (one per SM), 512 threads, warp tile 64x32
#define BM 128
#define BN 256
#define BK 32
#define CHUNKS (K_DIM / BK)      // 1536 (divisible by 3)
#define STAGES 3
#define LDA 40                   // 32 + 8 pad (bf16)
#define LDB 264                  // 256 + 8 pad (bf16)

// Per-stage smem byte offsets
#define AH_OFF 0
#define AL_OFF (BM * LDA * 2)                    // 10240
#define BH_OFF (2 * BM * LDA * 2)                // 20480
#define BL_OFF (2 * BM * LDA * 2 + BK * LDB * 2) // 37376
#define STAGE_B (2 * BM * LDA * 2 + 2 * BK * LDB * 2)   // 54272
#define DSMEM_BYTES (STAGES * STAGE_B)                  // 162816

// ---------------------------------------------------------------------------
// Device scratch (no cudaMalloc allowed; globals are zero-initialized)
// ---------------------------------------------------------------------------
__device__ __align__(16)  float         g_protoA[N_WAY * K_DIM];
__device__ __align__(16)  float         g_Z[M_TOT * N_DIM];
__device__                float         g_norms[M_TOT];
__device__ __align__(128) __nv_bfloat16 g_Xh[(size_t)M_PAD * K_DIM];
__device__ __align__(128) __nv_bfloat16 g_Xl[(size_t)M_PAD * K_DIM];
__device__ __align__(128) __nv_bfloat16 g_Wh[(size_t)K_DIM * N_DIM];
__device__ __align__(128) __nv_bfloat16 g_Wl[(size_t)K_DIM * N_DIM];

// ---------------------------------------------------------------------------
// Helpers
// ---------------------------------------------------------------------------
__device__ __forceinline__ uint32_t smem_u32(const void* p) {
    uint32_t a;
    asm("{ .reg .u64 t; cvta.to.shared.u64 t, %1; cvt.u32.u64 %0, t; }" : "=r"(a) : "l"(p));
    return a;
}
__device__ __forceinline__ void cp_async16(uint32_t dst, const void* src) {
    asm volatile("cp.async.cg.shared.global [%0], [%1], 16;" :: "r"(dst), "l"(src) : "memory");
}
__device__ __forceinline__ void cp_commit() {
    asm volatile("cp.async.commit_group;" ::: "memory");
}
template <int N>
__device__ __forceinline__ void cp_wait() {
    asm volatile("cp.async.wait_group %0;" :: "n"(N) : "memory");
}

// f32x4 -> packed hi bf16x4 (8B) + residual float4
__device__ __forceinline__ unsigned long long pack4_hi(float4 v, float4* rem) {
    __nv_bfloat16 h0 = __float2bfloat16(v.x), h1 = __float2bfloat16(v.y);
    __nv_bfloat16 h2 = __float2bfloat16(v.z), h3 = __float2bfloat16(v.w);
    rem->x = v.x - __bfloat162float(h0);
    rem->y = v.y - __bfloat162float(h1);
    rem->z = v.z - __bfloat162float(h2);
    rem->w = v.w - __bfloat162float(h3);
    unsigned a = (unsigned)__bfloat16_as_ushort(h0) | ((unsigned)__bfloat16_as_ushort(h1) << 16);
    unsigned b = (unsigned)__bfloat16_as_ushort(h2) | ((unsigned)__bfloat16_as_ushort(h3) << 16);
    return (unsigned long long)a | ((unsigned long long)b << 32);
}
__device__ __forceinline__ unsigned long long pack4(float4 v) {
    __nv_bfloat16 h0 = __float2bfloat16(v.x), h1 = __float2bfloat16(v.y);
    __nv_bfloat16 h2 = __float2bfloat16(v.z), h3 = __float2bfloat16(v.w);
    unsigned a = (unsigned)__bfloat16_as_ushort(h0) | ((unsigned)__bfloat16_as_ushort(h1) << 16);
    unsigned b = (unsigned)__bfloat16_as_ushort(h2) | ((unsigned)__bfloat16_as_ushort(h3) << 16);
    return (unsigned long long)a | ((unsigned long long)b << 32);
}

// ---------------------------------------------------------------------------
// Kernel 1: per-class mean of support images. grid (64, 16), block 256
// ---------------------------------------------------------------------------
__global__ void proto_mean_kernel(const float* __restrict__ support,
                                  const int* __restrict__ labels) {
    __shared__ int s_rows[N_SUP];
    __shared__ int s_cnt;
    const int c   = blockIdx.x;
    const int tid = threadIdx.x;

    if (tid < 32) {
        int cnt = 0;
        for (int base = 0; base < N_SUP; base += 32) {
            int lab = labels[base + tid];
            unsigned m = __ballot_sync(0xffffffffu, lab == c);
            if (lab == c)
                s_rows[cnt + __popc(m & ((1u << tid) - 1u))] = base + tid;
            cnt += __popc(m);
        }
        if (tid == 0) s_cnt = cnt;
    }
    __syncthreads();

    const int   n   = s_cnt;
    const float inv = 1.0f / (float)n;
    const int kchunk = K_DIM / gridDim.y;
    const int k0     = blockIdx.y * kchunk;

    for (int k = k0 + tid; k < k0 + kchunk; k += blockDim.x) {
        float s = 0.0f;
        for (int j = 0; j < n; j++)
            s += support[(size_t)s_rows[j] * K_DIM + k];
        g_protoA[c * K_DIM + k] = s * inv;
    }
}

// ---------------------------------------------------------------------------
// Kernel 2: split-convert X rows (protos first, then queries). grid 2112.
// ---------------------------------------------------------------------------
__global__ void convert_X_kernel(const float* __restrict__ query) {
    const int row = blockIdx.x;
    const float* src = (row < N_WAY) ? &g_protoA[(size_t)row * K_DIM]
                                     : &query[(size_t)(row - N_WAY) * K_DIM];
    __nv_bfloat16* dh = &g_Xh[(size_t)row * K_DIM];
    __nv_bfloat16* dl = &g_Xl[(size_t)row * K_DIM];
    for (int k4 = threadIdx.x * 4; k4 < K_DIM; k4 += blockDim.x * 4) {
        float4 v = *reinterpret_cast<const float4*>(&src[k4]);
        float4 rem;
        unsigned long long hi = pack4_hi(v, &rem);
        unsigned long long lo = pack4(rem);
        *reinterpret_cast<unsigned long long*>(&dh[k4]) = hi;
        *reinterpret_cast<unsigned long long*>(&dl[k4]) = lo;
    }
}

// ---------------------------------------------------------------------------
// Kernel 3: split-convert W (flat, layout preserved). grid 98304, block 256.
// ---------------------------------------------------------------------------
__global__ void convert_W_kernel(const float* __restrict__ W) {
    const size_t i4 = ((size_t)blockIdx.x * blockDim.x + threadIdx.x) * 4;
    float4 v = *reinterpret_cast<const float4*>(&W[i4]);
    float4 rem;
    unsigned long long hi = pack4_hi(v, &rem);
    unsigned long long lo = pack4(rem);
    *reinterpret_cast<unsigned long long*>(&g_Wh[i4]) = hi;
    *reinterpret_cast<unsigned long long*>(&g_Wl[i4]) = lo;
}

// ---------------------------------------------------------------------------
// Kernel 4: GEMM  Z[M_PAD, 2048] = X @ W  (3xbf16 split, f32 acc)
// grid (8 n-tiles, 17 m-tiles) = 136 CTAs (1/SM), block 512,
// 3-stage cp.async pipeline, one barrier per chunk.
// MMA inner order is TERM-MAJOR: dependent writes to the same accumulator
// are spaced 4 independent MMAs apart (RAW chain broken).
// ---------------------------------------------------------------------------
__device__ __forceinline__ void issue_stage(int c, uint32_t sb, int m0, int n0, int tid) {
    const int k0 = c * BK;
    // A: 128 rows x 32 cols bf16 = 4 x 16B segs/row; 512 idx, 1 per thread (hi+lo)
    {
        int r   = tid >> 2;                 // 0..127
        int seg = (tid & 3) * 8;            // bf16 elems
        uint32_t doff = (uint32_t)(r * LDA + seg) * 2u;
        cp_async16(sb + AH_OFF + doff, &g_Xh[(size_t)(m0 + r) * K_DIM + k0 + seg]);
        cp_async16(sb + AL_OFF + doff, &g_Xl[(size_t)(m0 + r) * K_DIM + k0 + seg]);
    }
    // B: 32 rows x 256 cols bf16 = 32 x 16B segs/row; 1024 idx, 2 per thread (hi+lo)
#pragma unroll
    for (int i = 0; i < 2; i++) {
        int idx = tid + i * 512;            // 0..1023
        int r   = idx >> 5;                 // 0..31
        int seg = (idx & 31) * 8;
        uint32_t doff = (uint32_t)(r * LDB + seg) * 2u;
        cp_async16(sb + BH_OFF + doff, &g_Wh[(size_t)(k0 + r) * N_DIM + n0 + seg]);
        cp_async16(sb + BL_OFF + doff, &g_Wl[(size_t)(k0 + r) * N_DIM + n0 + seg]);
    }
    cp_commit();
}

__global__ void __launch_bounds__(512, 1) gemm_wmma_kernel() {
    extern __shared__ char dsm[];
    const uint32_t smem_base = smem_u32(dsm);

    const int tid = threadIdx.x;
    const int n0  = blockIdx.x * BN;
    const int m0  = blockIdx.y * BM;
    const int warpId = tid >> 5;        // 0..15
    const int wm = warpId >> 3;         // 0..1 (64 rows)
    const int wn = warpId & 7;          // 0..7 (32 cols)

    wmma::fragment<wmma::accumulator, 16, 16, 16, float> acc[4][2];
#pragma unroll
    for (int mi = 0; mi < 4; mi++)
#pragma unroll
        for (int ni = 0; ni < 2; ni++)
            wmma::fill_fragment(acc[mi][ni], 0.0f);

    // prologue: 2 stages in flight
    issue_stage(0, smem_base + 0 * STAGE_B, m0, n0, tid);
    issue_stage(1, smem_base + 1 * STAGE_B, m0, n0, tid);

#define CHUNK_BODY(c, S)                                                              \
    {                                                                                 \
        cp_wait<1>();                                                                 \
        __syncthreads();                                                              \
        if ((c) + 2 < CHUNKS)                                                         \
            issue_stage((c) + 2, smem_base + (uint32_t)(((S) + 2) % STAGES) * STAGE_B,\
                        m0, n0, tid);                                                 \
        const char* sb = dsm + (S) * STAGE_B;                                         \
        const __nv_bfloat16* Ah = (const __nv_bfloat16*)(sb + AH_OFF);                \
        const __nv_bfloat16* Al = (const __nv_bfloat16*)(sb + AL_OFF);                \
        const __nv_bfloat16* Bh = (const __nv_bfloat16*)(sb + BH_OFF);                \
        const __nv_bfloat16* Bl = (const __nv_bfloat16*)(sb + BL_OFF);                \
        _Pragma("unroll")                                                             \
        for (int ks = 0; ks < 2; ks++) {                                              \
            const int kk = ks * 16;                                                   \
            wmma::fragment<wmma::matrix_a, 16, 16, 16, __nv_bfloat16,                 \
                           wmma::row_major> ah[4], al[4];                             \
            _Pragma("unroll")                                                         \
            for (int mi = 0; mi < 4; mi++) {                                          \
                wmma::load_matrix_sync(ah[mi], &Ah[(wm * 64 + mi * 16) * LDA + kk], LDA); \
                wmma::load_matrix_sync(al[mi], &Al[(wm * 64 + mi * 16) * LDA + kk], LDA); \
            }                                                                         \
            _Pragma("unroll")                                                         \
            for (int ni = 0; ni < 2; ni++) {                                          \
                wmma::fragment<wmma::matrix_b, 16, 16, 16, __nv_bfloat16,             \
                               wmma::row_major> bh, bl;                               \
                wmma::load_matrix_sync(bh, &Bh[kk * LDB + wn * 32 + ni * 16], LDB);   \
                wmma::load_matrix_sync(bl, &Bl[kk * LDB + wn * 32 + ni * 16], LDB);   \
                /* term-major: 4 independent MMAs between reuses of any acc */        \
                _Pragma("unroll")                                                     \
                for (int mi = 0; mi < 4; mi++)                                        \
                    wmma::mma_sync(acc[mi][ni], ah[mi], bh, acc[mi][ni]);             \
                _Pragma("unroll")                                                     \
                for (int mi = 0; mi < 4; mi++)                                        \
                    wmma::mma_sync(acc[mi][ni], ah[mi], bl, acc[mi][ni]);             \
                _Pragma("unroll")                                                     \
                for (int mi = 0; mi < 4; mi++)                                        \
                    wmma::mma_sync(acc[mi][ni], al[mi], bh, acc[mi][ni]);             \
            }                                                                         \
        }                                                                             \
    }

    for (int c = 0; c < CHUNKS; c += 3) {       // CHUNKS % 3 == 0
        CHUNK_BODY(c + 0, 0)
        CHUNK_BODY(c + 1, 1)
        CHUNK_BODY(c + 2, 2)
    }
#undef CHUNK_BODY

    cp_wait<0>();

    // epilogue: 64-row warp blocks are fully valid or fully padding (M_TOT%64==0)
    const int rowBase = m0 + wm * 64;
    if (rowBase < M_TOT) {
#pragma unroll
        for (int mi = 0; mi < 4; mi++)
#pragma unroll
            for (int ni = 0; ni < 2; ni++)
                wmma::store_matrix_sync(&g_Z[(size_t)(rowBase + mi * 16) * N_DIM + n0 + wn * 32 + ni * 16],
                                        acc[mi][ni], N_DIM, wmma::mem_row_major);
    }
}

// ---------------------------------------------------------------------------
// Kernel 5: Z += b (in place) and row norms. grid 2112, block 256.
// ---------------------------------------------------------------------------
__global__ void bias_norm_kernel(const float* __restrict__ b) {
    __shared__ float red[256];
    const int m   = blockIdx.x;
    const int tid = threadIdx.x;
    float* z = &g_Z[(size_t)m * N_DIM];
    float acc = 0.0f;
    for (int k = tid; k < N_DIM; k += 256) {
        float v = z[k] + b[k];
        z[k] = v;
        acc += v * v;
    }
    red[tid] = acc;
    __syncthreads();
    for (int s = 128; s > 0; s >>= 1) {
        if (tid < s) red[tid] += red[tid + s];
        __syncthreads();
    }
    if (tid == 0) g_norms[m] = sqrtf(red[0]);
}

// ---------------------------------------------------------------------------
// Kernel 6: cosine scores. grid 2048, block 256.
// ---------------------------------------------------------------------------
__global__ void scores_kernel(float* __restrict__ out) {
    __shared__ float q[N_DIM];
    const int qi   = blockIdx.x;
    const int tid  = threadIdx.x;
    const int warp = tid >> 5;
    const int lane = tid & 31;

    const float* qrow = &g_Z[(size_t)(N_WAY + qi) * N_DIM];
    for (int k = tid; k < N_DIM; k += 256) q[k] = qrow[k];
    __syncthreads();

    const float qn = g_norms[N_WAY + qi];
    for (int c = warp; c < N_WAY; c += 8) {
        const float* p = &g_Z[(size_t)c * N_DIM];
        float acc = 0.0f;
        for (int k = lane; k < N_DIM; k += 32)
            acc += q[k] * p[k];
#pragma unroll
        for (int off = 16; off > 0; off >>= 1)
            acc += __shfl_xor_sync(0xffffffffu, acc, off);
        if (lane == 0) {
            float d = fmaxf(qn * g_norms[c], EPS_CS);
            out[qi * N_WAY + c] = acc / d;
        }
    }
}

// ---------------------------------------------------------------------------
// Launch
// ---------------------------------------------------------------------------
extern "C" void kernel_launch(void* const* d_in, const int* in_sizes, int n_in,
                              void* d_out, int out_size) {
    const float* support = (const float*)d_in[0];   // [1024, 49152] f32
    const int*   labels  = (const int*)  d_in[1];   // [1024] i32
    const float* query   = (const float*)d_in[2];   // [2048, 49152] f32
    const float* W       = (const float*)d_in[3];   // [49152, 2048] f32
    const float* b       = (const float*)d_in[4];   // [2048] f32
    float*       out     = (float*)d_out;           // [2048, 64] f32

    cudaFuncSetAttribute(gemm_wmma_kernel,
                         cudaFuncAttributeMaxDynamicSharedMemorySize, DSMEM_BYTES);

    proto_mean_kernel<<<dim3(N_WAY, 16), 256>>>(support, labels);
    convert_X_kernel<<<M_TOT, 256>>>(query);
    convert_W_kernel<<<(K_DIM / 4) * (N_DIM / 256), 256>>>(W);
    gemm_wmma_kernel<<<dim3(N_DIM / BN, M_PAD / BM), 512, DSMEM_BYTES>>>();
    bias_norm_kernel<<<M_TOT, 256>>>(b);
    scores_kernel<<<N_QRY, 256>>>(out);
}

// round 13
// speedup vs baseline: 1.1476x; 1.0344x over previous
#include <cuda_runtime.h>
#include <cuda_bf16.h>
#include <mma.h>
#include <cstdint>
#include <cstddef>

using namespace nvcuda;

// ---------------------------------------------------------------------------
// Problem constants
// ---------------------------------------------------------------------------
#define K_DIM   49152
#define N_DIM   2048
#define N_WAY   64
#define N_SUP   1024
#define N_QRY   2048
#define M_TOT   2112             // 64 protos + 2048 queries
#define M_PAD   2176             // 17 * 128 (pad rows stay zero)
#define EPS_CS  1e-6f

// GEMM tiling: 136 CTAs (one per SM), 256 threads / 8 warps, warp tile 64x64
#define BM 128
#define BN 256
#define BK 32
#define CHUNKS (K_DIM / BK)      // 1536 (divisible by 3)
#define STAGES 3
#define LDA 40                   // 32 + 8 pad (bf16)
#define LDB 264                  // 256 + 8 pad (bf16)

// Per-stage smem byte offsets
#define AH_OFF 0
#define AL_OFF (BM * LDA * 2)                    // 10240
#define BH_OFF (2 * BM * LDA * 2)                // 20480
#define BL_OFF (2 * BM * LDA * 2 + BK * LDB * 2) // 37376
#define STAGE_B (2 * BM * LDA * 2 + 2 * BK * LDB * 2)   // 54272
#define DSMEM_BYTES (STAGES * STAGE_B)                  // 162816

// ---------------------------------------------------------------------------
// Device scratch (no cudaMalloc allowed; globals are zero-initialized)
// ---------------------------------------------------------------------------
__device__ __align__(16)  float         g_protoA[N_WAY * K_DIM];
__device__ __align__(16)  float         g_Z[M_TOT * N_DIM];
__device__                float         g_norms[M_TOT];
__device__ __align__(128) __nv_bfloat16 g_Xh[(size_t)M_PAD * K_DIM];
__device__ __align__(128) __nv_bfloat16 g_Xl[(size_t)M_PAD * K_DIM];
__device__ __align__(128) __nv_bfloat16 g_Wh[(size_t)K_DIM * N_DIM];
__device__ __align__(128) __nv_bfloat16 g_Wl[(size_t)K_DIM * N_DIM];

// ---------------------------------------------------------------------------
// Helpers
// ---------------------------------------------------------------------------
__device__ __forceinline__ uint32_t smem_u32(const void* p) {
    uint32_t a;
    asm("{ .reg .u64 t; cvta.to.shared.u64 t, %1; cvt.u32.u64 %0, t; }" : "=r"(a) : "l"(p));
    return a;
}
__device__ __forceinline__ void cp_async16(uint32_t dst, const void* src) {
    asm volatile("cp.async.cg.shared.global [%0], [%1], 16;" :: "r"(dst), "l"(src) : "memory");
}
__device__ __forceinline__ void cp_commit() {
    asm volatile("cp.async.commit_group;" ::: "memory");
}
template <int N>
__device__ __forceinline__ void cp_wait() {
    asm volatile("cp.async.wait_group %0;" :: "n"(N) : "memory");
}

// f32x4 -> packed hi bf16x4 (8B) + residual float4
__device__ __forceinline__ unsigned long long pack4_hi(float4 v, float4* rem) {
    __nv_bfloat16 h0 = __float2bfloat16(v.x), h1 = __float2bfloat16(v.y);
    __nv_bfloat16 h2 = __float2bfloat16(v.z), h3 = __float2bfloat16(v.w);
    rem->x = v.x - __bfloat162float(h0);
    rem->y = v.y - __bfloat162float(h1);
    rem->z = v.z - __bfloat162float(h2);
    rem->w = v.w - __bfloat162float(h3);
    unsigned a = (unsigned)__bfloat16_as_ushort(h0) | ((unsigned)__bfloat16_as_ushort(h1) << 16);
    unsigned b = (unsigned)__bfloat16_as_ushort(h2) | ((unsigned)__bfloat16_as_ushort(h3) << 16);
    return (unsigned long long)a | ((unsigned long long)b << 32);
}
__device__ __forceinline__ unsigned long long pack4(float4 v) {
    __nv_bfloat16 h0 = __float2bfloat16(v.x), h1 = __float2bfloat16(v.y);
    __nv_bfloat16 h2 = __float2bfloat16(v.z), h3 = __float2bfloat16(v.w);
    unsigned a = (unsigned)__bfloat16_as_ushort(h0) | ((unsigned)__bfloat16_as_ushort(h1) << 16);
    unsigned b = (unsigned)__bfloat16_as_ushort(h2) | ((unsigned)__bfloat16_as_ushort(h3) << 16);
    return (unsigned long long)a | ((unsigned long long)b << 32);
}

// ---------------------------------------------------------------------------
// Kernel 1: per-class mean of support images. grid (64, 16), block 256
// ---------------------------------------------------------------------------
__global__ void proto_mean_kernel(const float* __restrict__ support,
                                  const int* __restrict__ labels) {
    __shared__ int s_rows[N_SUP];
    __shared__ int s_cnt;
    const int c   = blockIdx.x;
    const int tid = threadIdx.x;

    if (tid < 32) {
        int cnt = 0;
        for (int base = 0; base < N_SUP; base += 32) {
            int lab = labels[base + tid];
            unsigned m = __ballot_sync(0xffffffffu, lab == c);
            if (lab == c)
                s_rows[cnt + __popc(m & ((1u << tid) - 1u))] = base + tid;
            cnt += __popc(m);
        }
        if (tid == 0) s_cnt = cnt;
    }
    __syncthreads();

    const int   n   = s_cnt;
    const float inv = 1.0f / (float)n;
    const int kchunk = K_DIM / gridDim.y;
    const int k0     = blockIdx.y * kchunk;

    for (int k = k0 + tid; k < k0 + kchunk; k += blockDim.x) {
        float s = 0.0f;
        for (int j = 0; j < n; j++)
            s += support[(size_t)s_rows[j] * K_DIM + k];
        g_protoA[c * K_DIM + k] = s * inv;
    }
}

// ---------------------------------------------------------------------------
// Kernel 2: split-convert X rows (protos first, then queries). grid 2112.
// ---------------------------------------------------------------------------
__global__ void convert_X_kernel(const float* __restrict__ query) {
    const int row = blockIdx.x;
    const float* src = (row < N_WAY) ? &g_protoA[(size_t)row * K_DIM]
                                     : &query[(size_t)(row - N_WAY) * K_DIM];
    __nv_bfloat16* dh = &g_Xh[(size_t)row * K_DIM];
    __nv_bfloat16* dl = &g_Xl[(size_t)row * K_DIM];
    for (int k4 = threadIdx.x * 4; k4 < K_DIM; k4 += blockDim.x * 4) {
        float4 v = *reinterpret_cast<const float4*>(&src[k4]);
        float4 rem;
        unsigned long long hi = pack4_hi(v, &rem);
        unsigned long long lo = pack4(rem);
        *reinterpret_cast<unsigned long long*>(&dh[k4]) = hi;
        *reinterpret_cast<unsigned long long*>(&dl[k4]) = lo;
    }
}

// ---------------------------------------------------------------------------
// Kernel 3: split-convert W (flat, layout preserved). grid 98304, block 256.
// ---------------------------------------------------------------------------
__global__ void convert_W_kernel(const float* __restrict__ W) {
    const size_t i4 = ((size_t)blockIdx.x * blockDim.x + threadIdx.x) * 4;
    float4 v = *reinterpret_cast<const float4*>(&W[i4]);
    float4 rem;
    unsigned long long hi = pack4_hi(v, &rem);
    unsigned long long lo = pack4(rem);
    *reinterpret_cast<unsigned long long*>(&g_Wh[i4]) = hi;
    *reinterpret_cast<unsigned long long*>(&g_Wl[i4]) = lo;
}

// ---------------------------------------------------------------------------
// Kernel 4: GEMM  Z[M_PAD, 2048] = X @ W  (3xbf16 split, f32 acc)
// grid (8 n-tiles, 17 m-tiles) = 136 CTAs (1/SM), block 256 (8 warps),
// warp tile 64x64 (CUTLASS geometry, ~224 regs/thread of 256 budget),
// 3-stage cp.async pipeline, one barrier per chunk.
// ---------------------------------------------------------------------------
__device__ __forceinline__ void issue_stage(int c, uint32_t sb, int m0, int n0, int tid) {
    const int k0 = c * BK;
    // A: 128 rows x 32 cols bf16 = 4 x 16B segs/row; 512 idx, hi+lo
#pragma unroll
    for (int i = 0; i < 2; i++) {
        int idx = tid + i * 256;            // 0..511
        int r   = idx >> 2;                 // 0..127
        int seg = (idx & 3) * 8;            // bf16 elems
        uint32_t doff = (uint32_t)(r * LDA + seg) * 2u;
        cp_async16(sb + AH_OFF + doff, &g_Xh[(size_t)(m0 + r) * K_DIM + k0 + seg]);
        cp_async16(sb + AL_OFF + doff, &g_Xl[(size_t)(m0 + r) * K_DIM + k0 + seg]);
    }
    // B: 32 rows x 256 cols bf16 = 32 x 16B segs/row; 1024 idx, hi+lo
#pragma unroll
    for (int i = 0; i < 4; i++) {
        int idx = tid + i * 256;            // 0..1023
        int r   = idx >> 5;                 // 0..31
        int seg = (idx & 31) * 8;
        uint32_t doff = (uint32_t)(r * LDB + seg) * 2u;
        cp_async16(sb + BH_OFF + doff, &g_Wh[(size_t)(k0 + r) * N_DIM + n0 + seg]);
        cp_async16(sb + BL_OFF + doff, &g_Wl[(size_t)(k0 + r) * N_DIM + n0 + seg]);
    }
    cp_commit();
}

__global__ void __launch_bounds__(256) gemm_wmma_kernel() {
    extern __shared__ char dsm[];
    const uint32_t smem_base = smem_u32(dsm);

    const int tid = threadIdx.x;
    const int n0  = blockIdx.x * BN;
    const int m0  = blockIdx.y * BM;
    const int warpId = tid >> 5;        // 0..7
    const int wm = warpId >> 2;         // 0..1 (64 rows)
    const int wn = warpId & 3;          // 0..3 (64 cols)

    wmma::fragment<wmma::accumulator, 16, 16, 16, float> acc[4][4];
#pragma unroll
    for (int mi = 0; mi < 4; mi++)
#pragma unroll
        for (int ni = 0; ni < 4; ni++)
            wmma::fill_fragment(acc[mi][ni], 0.0f);

    // prologue: 2 stages in flight
    issue_stage(0, smem_base + 0 * STAGE_B, m0, n0, tid);
    issue_stage(1, smem_base + 1 * STAGE_B, m0, n0, tid);

#define CHUNK_BODY(c, S)                                                              \
    {                                                                                 \
        cp_wait<1>();                                                                 \
        __syncthreads();                                                              \
        if ((c) + 2 < CHUNKS)                                                         \
            issue_stage((c) + 2, smem_base + (uint32_t)(((S) + 2) % STAGES) * STAGE_B,\
                        m0, n0, tid);                                                 \
        const char* sb = dsm + (S) * STAGE_B;                                         \
        const __nv_bfloat16* Ah = (const __nv_bfloat16*)(sb + AH_OFF);                \
        const __nv_bfloat16* Al = (const __nv_bfloat16*)(sb + AL_OFF);                \
        const __nv_bfloat16* Bh = (const __nv_bfloat16*)(sb + BH_OFF);                \
        const __nv_bfloat16* Bl = (const __nv_bfloat16*)(sb + BL_OFF);                \
        _Pragma("unroll")                                                             \
        for (int ks = 0; ks < 2; ks++) {                                              \
            const int kk = ks * 16;                                                   \
            wmma::fragment<wmma::matrix_a, 16, 16, 16, __nv_bfloat16,                 \
                           wmma::row_major> ah[4], al[4];                             \
            _Pragma("unroll")                                                         \
            for (int mi = 0; mi < 4; mi++) {                                          \
                wmma::load_matrix_sync(ah[mi], &Ah[(wm * 64 + mi * 16) * LDA + kk], LDA); \
                wmma::load_matrix_sync(al[mi], &Al[(wm * 64 + mi * 16) * LDA + kk], LDA); \
            }                                                                         \
            _Pragma("unroll")                                                         \
            for (int ni = 0; ni < 4; ni++) {                                          \
                wmma::fragment<wmma::matrix_b, 16, 16, 16, __nv_bfloat16,             \
                               wmma::row_major> bh, bl;                               \
                wmma::load_matrix_sync(bh, &Bh[kk * LDB + wn * 64 + ni * 16], LDB);   \
                wmma::load_matrix_sync(bl, &Bl[kk * LDB + wn * 64 + ni * 16], LDB);   \
                /* term-major: 4 independent MMAs between reuses of any acc */        \
                _Pragma("unroll")                                                     \
                for (int mi = 0; mi < 4; mi++)                                        \
                    wmma::mma_sync(acc[mi][ni], ah[mi], bh, acc[mi][ni]);             \
                _Pragma("unroll")                                                     \
                for (int mi = 0; mi < 4; mi++)                                        \
                    wmma::mma_sync(acc[mi][ni], ah[mi], bl, acc[mi][ni]);             \
                _Pragma("unroll")                                                     \
                for (int mi = 0; mi < 4; mi++)                                        \
                    wmma::mma_sync(acc[mi][ni], al[mi], bh, acc[mi][ni]);             \
            }                                                                         \
        }                                                                             \
    }

    for (int c = 0; c < CHUNKS; c += 3) {       // CHUNKS % 3 == 0
        CHUNK_BODY(c + 0, 0)
        CHUNK_BODY(c + 1, 1)
        CHUNK_BODY(c + 2, 2)
    }
#undef CHUNK_BODY

    cp_wait<0>();

    // epilogue: 64-row warp blocks are fully valid or fully padding (M_TOT%64==0)
    const int rowBase = m0 + wm * 64;
    if (rowBase < M_TOT) {
#pragma unroll
        for (int mi = 0; mi < 4; mi++)
#pragma unroll
            for (int ni = 0; ni < 4; ni++)
                wmma::store_matrix_sync(&g_Z[(size_t)(rowBase + mi * 16) * N_DIM + n0 + wn * 64 + ni * 16],
                                        acc[mi][ni], N_DIM, wmma::mem_row_major);
    }
}

// ---------------------------------------------------------------------------
// Kernel 5: Z += b (in place) and row norms. grid 2112, block 256.
// ---------------------------------------------------------------------------
__global__ void bias_norm_kernel(const float* __restrict__ b) {
    __shared__ float red[256];
    const int m   = blockIdx.x;
    const int tid = threadIdx.x;
    float* z = &g_Z[(size_t)m * N_DIM];
    float acc = 0.0f;
    for (int k = tid; k < N_DIM; k += 256) {
        float v = z[k] + b[k];
        z[k] = v;
        acc += v * v;
    }
    red[tid] = acc;
    __syncthreads();
    for (int s = 128; s > 0; s >>= 1) {
        if (tid < s) red[tid] += red[tid + s];
        __syncthreads();
    }
    if (tid == 0) g_norms[m] = sqrtf(red[0]);
}

// ---------------------------------------------------------------------------
// Kernel 6: cosine scores. grid 2048, block 256.
// ---------------------------------------------------------------------------
__global__ void scores_kernel(float* __restrict__ out) {
    __shared__ float q[N_DIM];
    const int qi   = blockIdx.x;
    const int tid  = threadIdx.x;
    const int warp = tid >> 5;
    const int lane = tid & 31;

    const float* qrow = &g_Z[(size_t)(N_WAY + qi) * N_DIM];
    for (int k = tid; k < N_DIM; k += 256) q[k] = qrow[k];
    __syncthreads();

    const float qn = g_norms[N_WAY + qi];
    for (int c = warp; c < N_WAY; c += 8) {
        const float* p = &g_Z[(size_t)c * N_DIM];
        float acc = 0.0f;
        for (int k = lane; k < N_DIM; k += 32)
            acc += q[k] * p[k];
#pragma unroll
        for (int off = 16; off > 0; off >>= 1)
            acc += __shfl_xor_sync(0xffffffffu, acc, off);
        if (lane == 0) {
            float d = fmaxf(qn * g_norms[c], EPS_CS);
            out[qi * N_WAY + c] = acc / d;
        }
    }
}

// ---------------------------------------------------------------------------
// Launch
// ---------------------------------------------------------------------------
extern "C" void kernel_launch(void* const* d_in, const int* in_sizes, int n_in,
                              void* d_out, int out_size) {
    const float* support = (const float*)d_in[0];   // [1024, 49152] f32
    const int*   labels  = (const int*)  d_in[1];   // [1024] i32
    const float* query   = (const float*)d_in[2];   // [2048, 49152] f32
    const float* W       = (const float*)d_in[3];   // [49152, 2048] f32
    const float* b       = (const float*)d_in[4];   // [2048] f32
    float*       out     = (float*)d_out;           // [2048, 64] f32

    cudaFuncSetAttribute(gemm_wmma_kernel,
                         cudaFuncAttributeMaxDynamicSharedMemorySize, DSMEM_BYTES);

    proto_mean_kernel<<<dim3(N_WAY, 16), 256>>>(support, labels);
    convert_X_kernel<<<M_TOT, 256>>>(query);
    convert_W_kernel<<<(K_DIM / 4) * (N_DIM / 256), 256>>>(W);
    gemm_wmma_kernel<<<dim3(N_DIM / BN, M_PAD / BM), 256, DSMEM_BYTES>>>();
    bias_norm_kernel<<<M_TOT, 256>>>(b);
    scores_kernel<<<N_QRY, 256>>>(out);
}

// round 15
// speedup vs baseline: 1.1535x; 1.0051x over previous
#include <cuda_runtime.h>
#include <cuda_bf16.h>
#include <mma.h>
#include <cstdint>
#include <cstddef>

using namespace nvcuda;

// ---------------------------------------------------------------------------
// Problem constants
// ---------------------------------------------------------------------------
#define K_DIM   49152
#define N_DIM   2048
#define N_WAY   64
#define N_SUP   1024
#define N_QRY   2048
#define M_TOT   2112             // 64 protos + 2048 queries
#define M_PAD   2176             // 17 * 128 (pad rows stay zero)
#define EPS_CS  1e-6f

// GEMM tiling: 136 CTAs (one per SM), 256 threads / 8 warps, warp tile 64x64
#define BM 128
#define BN 256
#define BK 32
#define CHUNKS (K_DIM / BK)      // 1536 (divisible by 3)
#define STAGES 3
#define LDA 40                   // 32 + 8 pad (bf16)
#define LDB 264                  // 256 + 8 pad (bf16)

// Per-stage smem byte offsets
#define AH_OFF 0
#define AL_OFF (BM * LDA * 2)                    // 10240
#define BH_OFF (2 * BM * LDA * 2)                // 20480
#define BL_OFF (2 * BM * LDA * 2 + BK * LDB * 2) // 37376
#define STAGE_B (2 * BM * LDA * 2 + 2 * BK * LDB * 2)   // 54272
#define DSMEM_BYTES (STAGES * STAGE_B)                  // 162816

// ---------------------------------------------------------------------------
// Device scratch (no cudaMalloc allowed; globals are zero-initialized)
// ---------------------------------------------------------------------------
__device__ __align__(16)  float         g_protoA[N_WAY * K_DIM];
__device__ __align__(16)  float         g_Z[M_TOT * N_DIM];
__device__                float         g_norms[M_TOT];
__device__ __align__(128) __nv_bfloat16 g_Xh[(size_t)M_PAD * K_DIM];
__device__ __align__(128) __nv_bfloat16 g_Xl[(size_t)M_PAD * K_DIM];
__device__ __align__(128) __nv_bfloat16 g_Wh[(size_t)K_DIM * N_DIM];
__device__ __align__(128) __nv_bfloat16 g_Wl[(size_t)K_DIM * N_DIM];

// ---------------------------------------------------------------------------
// Helpers
// ---------------------------------------------------------------------------
__device__ __forceinline__ uint32_t smem_u32(const void* p) {
    uint32_t a;
    asm("{ .reg .u64 t; cvta.to.shared.u64 t, %1; cvt.u32.u64 %0, t; }" : "=r"(a) : "l"(p));
    return a;
}
__device__ __forceinline__ void cp_async16(uint32_t dst, const void* src) {
    asm volatile("cp.async.cg.shared.global [%0], [%1], 16;" :: "r"(dst), "l"(src) : "memory");
}
__device__ __forceinline__ void cp_commit() {
    asm volatile("cp.async.commit_group;" ::: "memory");
}
template <int N>
__device__ __forceinline__ void cp_wait() {
    asm volatile("cp.async.wait_group %0;" :: "n"(N) : "memory");
}

// f32x4 -> packed hi bf16x4 (8B) + residual float4
__device__ __forceinline__ unsigned long long pack4_hi(float4 v, float4* rem) {
    __nv_bfloat16 h0 = __float2bfloat16(v.x), h1 = __float2bfloat16(v.y);
    __nv_bfloat16 h2 = __float2bfloat16(v.z), h3 = __float2bfloat16(v.w);
    rem->x = v.x - __bfloat162float(h0);
    rem->y = v.y - __bfloat162float(h1);
    rem->z = v.z - __bfloat162float(h2);
    rem->w = v.w - __bfloat162float(h3);
    unsigned a = (unsigned)__bfloat16_as_ushort(h0) | ((unsigned)__bfloat16_as_ushort(h1) << 16);
    unsigned b = (unsigned)__bfloat16_as_ushort(h2) | ((unsigned)__bfloat16_as_ushort(h3) << 16);
    return (unsigned long long)a | ((unsigned long long)b << 32);
}
__device__ __forceinline__ unsigned long long pack4(float4 v) {
    __nv_bfloat16 h0 = __float2bfloat16(v.x), h1 = __float2bfloat16(v.y);
    __nv_bfloat16 h2 = __float2bfloat16(v.z), h3 = __float2bfloat16(v.w);
    unsigned a = (unsigned)__bfloat16_as_ushort(h0) | ((unsigned)__bfloat16_as_ushort(h1) << 16);
    unsigned b = (unsigned)__bfloat16_as_ushort(h2) | ((unsigned)__bfloat16_as_ushort(h3) << 16);
    return (unsigned long long)a | ((unsigned long long)b << 32);
}

// ---------------------------------------------------------------------------
// Kernel 1: per-class mean of support images. grid (64, 16), block 256
// ---------------------------------------------------------------------------
__global__ void proto_mean_kernel(const float* __restrict__ support,
                                  const int* __restrict__ labels) {
    __shared__ int s_rows[N_SUP];
    __shared__ int s_cnt;
    const int c   = blockIdx.x;
    const int tid = threadIdx.x;

    if (tid < 32) {
        int cnt = 0;
        for (int base = 0; base < N_SUP; base += 32) {
            int lab = labels[base + tid];
            unsigned m = __ballot_sync(0xffffffffu, lab == c);
            if (lab == c)
                s_rows[cnt + __popc(m & ((1u << tid) - 1u))] = base + tid;
            cnt += __popc(m);
        }
        if (tid == 0) s_cnt = cnt;
    }
    __syncthreads();

    const int   n   = s_cnt;
    const float inv = 1.0f / (float)n;
    const int kchunk = K_DIM / gridDim.y;
    const int k0     = blockIdx.y * kchunk;

    for (int k = k0 + tid; k < k0 + kchunk; k += blockDim.x) {
        float s = 0.0f;
        for (int j = 0; j < n; j++)
            s += support[(size_t)s_rows[j] * K_DIM + k];
        g_protoA[c * K_DIM + k] = s * inv;
    }
}

// ---------------------------------------------------------------------------
// Kernel 2: split-convert X rows (protos first, then queries). grid 2112.
// ---------------------------------------------------------------------------
__global__ void convert_X_kernel(const float* __restrict__ query) {
    const int row = blockIdx.x;
    const float* src = (row < N_WAY) ? &g_protoA[(size_t)row * K_DIM]
                                     : &query[(size_t)(row - N_WAY) * K_DIM];
    __nv_bfloat16* dh = &g_Xh[(size_t)row * K_DIM];
    __nv_bfloat16* dl = &g_Xl[(size_t)row * K_DIM];
    for (int k4 = threadIdx.x * 4; k4 < K_DIM; k4 += blockDim.x * 4) {
        float4 v = *reinterpret_cast<const float4*>(&src[k4]);
        float4 rem;
        unsigned long long hi = pack4_hi(v, &rem);
        unsigned long long lo = pack4(rem);
        *reinterpret_cast<unsigned long long*>(&dh[k4]) = hi;
        *reinterpret_cast<unsigned long long*>(&dl[k4]) = lo;
    }
}

// ---------------------------------------------------------------------------
// Kernel 3: split-convert W (flat, layout preserved). grid 98304, block 256.
// ---------------------------------------------------------------------------
__global__ void convert_W_kernel(const float* __restrict__ W) {
    const size_t i4 = ((size_t)blockIdx.x * blockDim.x + threadIdx.x) * 4;
    float4 v = *reinterpret_cast<const float4*>(&W[i4]);
    float4 rem;
    unsigned long long hi = pack4_hi(v, &rem);
    unsigned long long lo = pack4(rem);
    *reinterpret_cast<unsigned long long*>(&g_Wh[i4]) = hi;
    *reinterpret_cast<unsigned long long*>(&g_Wl[i4]) = lo;
}

// ---------------------------------------------------------------------------
// Kernel 4: GEMM  Z[M_PAD, 2048] = X @ W  (3xbf16 split, f32 acc)
// grid (8 n-tiles, 17 m-tiles) = 136 CTAs (1/SM), block 256 (8 warps),
// warp tile 64x64, 3-stage cp.async pipeline, one barrier per chunk.
// Inner loop is PASS-STRUCTURED: hh-pass, hl-pass, lh-pass per k-step.
// Live fragment set: acc(128) + 3 x 16 regs -> ~176 regs, freeing
// scheduling headroom vs the previous 255-reg ceiling.
// ---------------------------------------------------------------------------
__device__ __forceinline__ void issue_stage(int c, uint32_t sb, int m0, int n0, int tid) {
    const int k0 = c * BK;
    // A: 128 rows x 32 cols bf16 = 4 x 16B segs/row; 512 idx, hi+lo
#pragma unroll
    for (int i = 0; i < 2; i++) {
        int idx = tid + i * 256;            // 0..511
        int r   = idx >> 2;                 // 0..127
        int seg = (idx & 3) * 8;            // bf16 elems
        uint32_t doff = (uint32_t)(r * LDA + seg) * 2u;
        cp_async16(sb + AH_OFF + doff, &g_Xh[(size_t)(m0 + r) * K_DIM + k0 + seg]);
        cp_async16(sb + AL_OFF + doff, &g_Xl[(size_t)(m0 + r) * K_DIM + k0 + seg]);
    }
    // B: 32 rows x 256 cols bf16 = 32 x 16B segs/row; 1024 idx, hi+lo
#pragma unroll
    for (int i = 0; i < 4; i++) {
        int idx = tid + i * 256;            // 0..1023
        int r   = idx >> 5;                 // 0..31
        int seg = (idx & 31) * 8;
        uint32_t doff = (uint32_t)(r * LDB + seg) * 2u;
        cp_async16(sb + BH_OFF + doff, &g_Wh[(size_t)(k0 + r) * N_DIM + n0 + seg]);
        cp_async16(sb + BL_OFF + doff, &g_Wl[(size_t)(k0 + r) * N_DIM + n0 + seg]);
    }
    cp_commit();
}

__global__ void __launch_bounds__(256) gemm_wmma_kernel() {
    extern __shared__ char dsm[];
    const uint32_t smem_base = smem_u32(dsm);

    const int tid = threadIdx.x;
    const int n0  = blockIdx.x * BN;
    const int m0  = blockIdx.y * BM;
    const int warpId = tid >> 5;        // 0..7
    const int wm = warpId >> 2;         // 0..1 (64 rows)
    const int wn = warpId & 3;          // 0..3 (64 cols)

    wmma::fragment<wmma::accumulator, 16, 16, 16, float> acc[4][4];
#pragma unroll
    for (int mi = 0; mi < 4; mi++)
#pragma unroll
        for (int ni = 0; ni < 4; ni++)
            wmma::fill_fragment(acc[mi][ni], 0.0f);

    // prologue: 2 stages in flight
    issue_stage(0, smem_base + 0 * STAGE_B, m0, n0, tid);
    issue_stage(1, smem_base + 1 * STAGE_B, m0, n0, tid);

#define CHUNK_BODY(c, S)                                                              \
    {                                                                                 \
        cp_wait<1>();                                                                 \
        __syncthreads();                                                              \
        if ((c) + 2 < CHUNKS)                                                         \
            issue_stage((c) + 2, smem_base + (uint32_t)(((S) + 2) % STAGES) * STAGE_B,\
                        m0, n0, tid);                                                 \
        const char* sb = dsm + (S) * STAGE_B;                                         \
        const __nv_bfloat16* Ah = (const __nv_bfloat16*)(sb + AH_OFF);                \
        const __nv_bfloat16* Al = (const __nv_bfloat16*)(sb + AL_OFF);                \
        const __nv_bfloat16* Bh = (const __nv_bfloat16*)(sb + BH_OFF);                \
        const __nv_bfloat16* Bl = (const __nv_bfloat16*)(sb + BL_OFF);                \
        _Pragma("unroll")                                                             \
        for (int ks = 0; ks < 2; ks++) {                                              \
            const int kk = ks * 16;                                                   \
            wmma::fragment<wmma::matrix_a, 16, 16, 16, __nv_bfloat16,                 \
                           wmma::row_major> af[4];                                    \
            wmma::fragment<wmma::matrix_b, 16, 16, 16, __nv_bfloat16,                 \
                           wmma::row_major> bh[4], bx[4];                             \
            /* hh pass: af = Ah, bh = Bh */                                           \
            _Pragma("unroll")                                                         \
            for (int mi = 0; mi < 4; mi++)                                            \
                wmma::load_matrix_sync(af[mi], &Ah[(wm * 64 + mi * 16) * LDA + kk], LDA); \
            _Pragma("unroll")                                                         \
            for (int ni = 0; ni < 4; ni++)                                            \
                wmma::load_matrix_sync(bh[ni], &Bh[kk * LDB + wn * 64 + ni * 16], LDB);   \
            _Pragma("unroll")                                                         \
            for (int ni = 0; ni < 4; ni++)                                            \
                _Pragma("unroll")                                                     \
                for (int mi = 0; mi < 4; mi++)                                        \
                    wmma::mma_sync(acc[mi][ni], af[mi], bh[ni], acc[mi][ni]);         \
            /* hl pass: bx = Bl (af still Ah) */                                      \
            _Pragma("unroll")                                                         \
            for (int ni = 0; ni < 4; ni++)                                            \
                wmma::load_matrix_sync(bx[ni], &Bl[kk * LDB + wn * 64 + ni * 16], LDB);   \
            _Pragma("unroll")                                                         \
            for (int ni = 0; ni < 4; ni++)                                            \
                _Pragma("unroll")                                                     \
                for (int mi = 0; mi < 4; mi++)                                        \
                    wmma::mma_sync(acc[mi][ni], af[mi], bx[ni], acc[mi][ni]);         \
            /* lh pass: af = Al (overwrites Ah), uses bh */                           \
            _Pragma("unroll")                                                         \
            for (int mi = 0; mi < 4; mi++)                                            \
                wmma::load_matrix_sync(af[mi], &Al[(wm * 64 + mi * 16) * LDA + kk], LDA); \
            _Pragma("unroll")                                                         \
            for (int ni = 0; ni < 4; ni++)                                            \
                _Pragma("unroll")                                                     \
                for (int mi = 0; mi < 4; mi++)                                        \
                    wmma::mma_sync(acc[mi][ni], af[mi], bh[ni], acc[mi][ni]);         \
        }                                                                             \
    }

    for (int c = 0; c < CHUNKS; c += 3) {       // CHUNKS % 3 == 0
        CHUNK_BODY(c + 0, 0)
        CHUNK_BODY(c + 1, 1)
        CHUNK_BODY(c + 2, 2)
    }
#undef CHUNK_BODY

    cp_wait<0>();

    // epilogue: 64-row warp blocks are fully valid or fully padding (M_TOT%64==0)
    const int rowBase = m0 + wm * 64;
    if (rowBase < M_TOT) {
#pragma unroll
        for (int mi = 0; mi < 4; mi++)
#pragma unroll
            for (int ni = 0; ni < 4; ni++)
                wmma::store_matrix_sync(&g_Z[(size_t)(rowBase + mi * 16) * N_DIM + n0 + wn * 64 + ni * 16],
                                        acc[mi][ni], N_DIM, wmma::mem_row_major);
    }
}

// ---------------------------------------------------------------------------
// Kernel 5: Z += b (in place) and row norms. grid 2112, block 256.
// ---------------------------------------------------------------------------
__global__ void bias_norm_kernel(const float* __restrict__ b) {
    __shared__ float red[256];
    const int m   = blockIdx.x;
    const int tid = threadIdx.x;
    float* z = &g_Z[(size_t)m * N_DIM];
    float acc = 0.0f;
    for (int k = tid; k < N_DIM; k += 256) {
        float v = z[k] + b[k];
        z[k] = v;
        acc += v * v;
    }
    red[tid] = acc;
    __syncthreads();
    for (int s = 128; s > 0; s >>= 1) {
        if (tid < s) red[tid] += red[tid + s];
        __syncthreads();
    }
    if (tid == 0) g_norms[m] = sqrtf(red[0]);
}

// ---------------------------------------------------------------------------
// Kernel 6: cosine scores. grid 2048, block 256.
// ---------------------------------------------------------------------------
__global__ void scores_kernel(float* __restrict__ out) {
    __shared__ float q[N_DIM];
    const int qi   = blockIdx.x;
    const int tid  = threadIdx.x;
    const int warp = tid >> 5;
    const int lane = tid & 31;

    const float* qrow = &g_Z[(size_t)(N_WAY + qi) * N_DIM];
    for (int k = tid; k < N_DIM; k += 256) q[k] = qrow[k];
    __syncthreads();

    const float qn = g_norms[N_WAY + qi];
    for (int c = warp; c < N_WAY; c += 8) {
        const float* p = &g_Z[(size_t)c * N_DIM];
        float acc = 0.0f;
        for (int k = lane; k < N_DIM; k += 32)
            acc += q[k] * p[k];
#pragma unroll
        for (int off = 16; off > 0; off >>= 1)
            acc += __shfl_xor_sync(0xffffffffu, acc, off);
        if (lane == 0) {
            float d = fmaxf(qn * g_norms[c], EPS_CS);
            out[qi * N_WAY + c] = acc / d;
        }
    }
}

// ---------------------------------------------------------------------------
// Launch
// ---------------------------------------------------------------------------
extern "C" void kernel_launch(void* const* d_in, const int* in_sizes, int n_in,
                              void* d_out, int out_size) {
    const float* support = (const float*)d_in[0];   // [1024, 49152] f32
    const int*   labels  = (const int*)  d_in[1];   // [1024] i32
    const float* query   = (const float*)d_in[2];   // [2048, 49152] f32
    const float* W       = (const float*)d_in[3];   // [49152, 2048] f32
    const float* b       = (const float*)d_in[4];   // [2048] f32
    float*       out     = (float*)d_out;           // [2048, 64] f32

    cudaFuncSetAttribute(gemm_wmma_kernel,
                         cudaFuncAttributeMaxDynamicSharedMemorySize, DSMEM_BYTES);

    proto_mean_kernel<<<dim3(N_WAY, 16), 256>>>(support, labels);
    convert_X_kernel<<<M_TOT, 256>>>(query);
    convert_W_kernel<<<(K_DIM / 4) * (N_DIM / 256), 256>>>(W);
    gemm_wmma_kernel<<<dim3(N_DIM / BN, M_PAD / BM), 256, DSMEM_BYTES>>>();
    bias_norm_kernel<<<M_TOT, 256>>>(b);
    scores_kernel<<<N_QRY, 256>>>(out);
}